// round 12
// baseline (speedup 1.0000x reference)
#include <cuda_runtime.h>
#include <cstdint>

#define SEQ 2048
#define DH 64
#define NTH 256
#define CLS2 23.0f           // fixed shift in log2 domain; |s2| <~ 8.5 << 23
#define CK 64
#define NCH (SEQ / CK)
#define QSCALE 0.18033688f   // 0.125 * log2(e)

// smem byte offsets
#define OFF_K0 0             // K2 tile: 64 rows * 36 f2 * 8B = 18432
#define OFF_K1 18432
#define OFF_V0 36864         // V2 tile: 32 prows * 68 f2 * 8B = 17408
#define OFF_V1 54272
#define OFF_MB 71680         // per-warp mask words: 8*34*4 = 1088
#define SM_TOTAL 72768

__device__ float g_linv[32 * SEQ];

__device__ __forceinline__ float tf32f(float x) {
    unsigned u; asm("cvt.rna.tf32.f32 %0, %1;" : "=r"(u) : "f"(x));
    return __uint_as_float(u);
}
__device__ __forceinline__ unsigned tf32u(float x) {
    unsigned u; asm("cvt.rna.tf32.f32 %0, %1;" : "=r"(u) : "f"(x));
    return u;
}
__device__ __forceinline__ float ex2(float x) {
    float r; asm("ex2.approx.ftz.f32 %0, %1;" : "=f"(r) : "f"(x));
    return r;
}
__device__ __forceinline__ void mma_tf32(float* c, const unsigned* a, const unsigned* b) {
    asm volatile(
        "mma.sync.aligned.m16n8k8.row.col.f32.tf32.tf32.f32 "
        "{%0,%1,%2,%3}, {%4,%5,%6,%7}, {%8,%9}, {%0,%1,%2,%3};"
        : "+f"(c[0]), "+f"(c[1]), "+f"(c[2]), "+f"(c[3])
        : "r"(a[0]), "r"(a[1]), "r"(a[2]), "r"(a[3]), "r"(b[0]), "r"(b[1]));
}
__device__ __forceinline__ bool mask_is_int32(const unsigned* m) {
    unsigned acc = 0;
#pragma unroll
    for (int i = 0; i < 64; i++) acc |= m[i];
    return acc <= 1u;
}

// K [64][64] -> K2 paired-column tile: K2[r][ks*4+j] = {K[r][ks*8+j], K[r][ks*8+j+4]}
// row stride 36 f2 (=72 f32); tf32-rounded
__device__ __forceinline__ void stage_K2(const float* __restrict__ src, float* __restrict__ dst) {
#pragma unroll
    for (int i = 0; i < 4; i++) {
        int u = threadIdx.x + i * NTH;
        int r = u >> 4, c4 = (u & 15) * 4;
        float4 v = *(const float4*)(src + (size_t)r * DH + c4);
        int ks = c4 >> 3;
        int half = (c4 >> 2) & 1;
        float* base = dst + r * 72 + ks * 8 + half;
        base[0] = tf32f(v.x); base[2] = tf32f(v.y);
        base[4] = tf32f(v.z); base[6] = tf32f(v.w);
    }
}
// V [64][64] -> V2 paired-row tile: V2[g*4+j][d] = {V[g*8+j][d], V[g*8+j+4][d]}
// prow stride 68 f2 (=136 f32); tf32-rounded
__device__ __forceinline__ void stage_V2(const float* __restrict__ src, float* __restrict__ dst) {
#pragma unroll
    for (int i = 0; i < 4; i++) {
        int u = threadIdx.x + i * NTH;
        int r = u >> 4, c4 = (u & 15) * 4;
        float4 v = *(const float4*)(src + (size_t)r * DH + c4);
        int pr = ((r >> 3) << 2) + (r & 3);
        int half = (r >> 2) & 1;
        float* base = dst + pr * 136 + c4 * 2 + half;
        base[0] = tf32f(v.x); base[2] = tf32f(v.y);
        base[4] = tf32f(v.z); base[6] = tf32f(v.w);
    }
}

__global__ void __launch_bounds__(NTH, 2)
attn_main(const float* __restrict__ Q, const float* __restrict__ K,
          const float* __restrict__ V, const void* __restrict__ mraw,
          float* __restrict__ prob, float* __restrict__ ctx) {
    extern __shared__ char smem[];
    const int tid = threadIdx.x, w = tid >> 5, lane = tid & 31;
    const int tg = lane >> 2, tq = lane & 3;
    const int bh = blockIdx.y, q0 = blockIdx.x * 128;

    const float* Qb = Q + (size_t)bh * SEQ * DH;
    const float* Kb = K + (size_t)bh * SEQ * DH;
    const float* Vb = V + (size_t)bh * SEQ * DH;
    float* Pb = prob + (size_t)bh * SEQ * SEQ;
    float* Cb = ctx + (size_t)bh * SEQ * DH;

    const bool m32 = mask_is_int32((const unsigned*)mraw);
    const int r0 = w * 16 + tg, r1 = r0 + 8;

    // ---- prologue: Q frags via transient smem ----
    {
        float* Qs = (float*)smem;
#pragma unroll
        for (int i = 0; i < 8; i++) {
            int u = tid + i * NTH;
            int r = u >> 4, c4 = (u & 15) * 4;
            *(float4*)(Qs + r * 64 + c4) = *(const float4*)(Qb + (size_t)(q0 + r) * DH + c4);
        }
    }
    __syncthreads();
    unsigned aQ[8][4];
    {
        const float* Qs = (const float*)smem;
        const float* q0p = Qs + r0 * 64;
        const float* q1p = Qs + r1 * 64;
#pragma unroll
        for (int ks = 0; ks < 8; ks++) {
            int j = ks * 8 + tq;
            aQ[ks][0] = tf32u(q0p[j] * QSCALE);
            aQ[ks][1] = tf32u(q1p[j] * QSCALE);
            aQ[ks][2] = tf32u(q0p[j + 4] * QSCALE);
            aQ[ks][3] = tf32u(q1p[j + 4] * QSCALE);
        }
    }
    __syncthreads();

    stage_K2(Kb, (float*)(smem + OFF_K0));
    stage_V2(Vb, (float*)(smem + OFF_V0));
    __syncthreads();

    float acc[8][4];
#pragma unroll
    for (int nv = 0; nv < 8; nv++) {
        acc[nv][0] = 0.f; acc[nv][1] = 0.f; acc[nv][2] = 0.f; acc[nv][3] = 0.f;
    }
    float ls0 = 0.f, ls1 = 0.f;
    const int s0 = tq >> 1, par = tq & 1;
    unsigned* MB = (unsigned*)(smem + OFF_MB) + w * 34;

    for (int c = 0; c < NCH; c++) {
        // prefetch next chunk into the other buffers (LDGs overlap compute below)
        if (c + 1 < NCH) {
            stage_K2(Kb + (size_t)(c + 1) * CK * DH,
                     (float*)(smem + ((c & 1) ? OFF_K0 : OFF_K1)));
            stage_V2(Vb + (size_t)(c + 1) * CK * DH,
                     (float*)(smem + ((c & 1) ? OFF_V0 : OFF_V1)));
        }
        // inline mask ballots: this warp's 16 rows x 64 cols -> 32 words
        if (m32) {
            const int* Mi = (const int*)mraw + (size_t)bh * SEQ * SEQ;
#pragma unroll 4
            for (int j = 0; j < 16; j++) {
                const int* row = Mi + (size_t)(q0 + w * 16 + j) * SEQ + c * CK;
                unsigned b0 = __ballot_sync(0xffffffffu, row[lane] != 0);
                unsigned b1 = __ballot_sync(0xffffffffu, row[32 + lane] != 0);
                if (lane == 0) { MB[j * 2] = b0; MB[j * 2 + 1] = b1; }
            }
        } else {
            const unsigned char* Mc = (const unsigned char*)mraw + (size_t)bh * SEQ * SEQ;
#pragma unroll 4
            for (int j = 0; j < 16; j++) {
                const unsigned char* row = Mc + (size_t)(q0 + w * 16 + j) * SEQ + c * CK;
                unsigned b0 = __ballot_sync(0xffffffffu, row[lane] != 0);
                unsigned b1 = __ballot_sync(0xffffffffu, row[32 + lane] != 0);
                if (lane == 0) { MB[j * 2] = b0; MB[j * 2 + 1] = b1; }
            }
        }
        __syncwarp();
        const unsigned mA0 = MB[tg * 2],       mA1 = MB[tg * 2 + 1];
        const unsigned mB0 = MB[(tg + 8) * 2], mB1 = MB[(tg + 8) * 2 + 1];

        const float2* Kf = (const float2*)(smem + ((c & 1) ? OFF_K1 : OFF_K0));
        const float2* Vf = (const float2*)(smem + ((c & 1) ? OFF_V1 : OFF_V0));

#pragma unroll
        for (int g = 0; g < 8; g++) {
            float c0[4] = {0.f, 0.f, 0.f, 0.f};
            float c1[4] = {0.f, 0.f, 0.f, 0.f};
            const float2* Kr = Kf + (g * 8 + tg) * 36 + tq;
#pragma unroll
            for (int ks = 0; ks < 8; ks += 2) {
                float2 kb0 = Kr[ks * 4];
                float2 kb1 = Kr[ks * 4 + 4];
                unsigned b0[2] = {__float_as_uint(kb0.x), __float_as_uint(kb0.y)};
                unsigned b1[2] = {__float_as_uint(kb1.x), __float_as_uint(kb1.y)};
                mma_tf32(c0, aQ[ks], b0);
                mma_tf32(c1, aQ[ks + 1], b1);
            }
            const unsigned mw0 = (g < 4) ? mA0 : mA1;
            const unsigned mw1 = (g < 4) ? mB0 : mB1;
            const int sh = (g & 3) * 8 + tq * 2;
            float p0 = ((mw0 >> sh) & 1)       ? 0.f : ex2(c0[0] + c1[0] - CLS2);
            float p1 = ((mw0 >> (sh + 1)) & 1) ? 0.f : ex2(c0[1] + c1[1] - CLS2);
            float p2 = ((mw1 >> sh) & 1)       ? 0.f : ex2(c0[2] + c1[2] - CLS2);
            float p3 = ((mw1 >> (sh + 1)) & 1) ? 0.f : ex2(c0[3] + c1[3] - CLS2);
            ls0 += p0 + p1;
            ls1 += p2 + p3;

            // raw (unnormalized) probs -> gmem; normalized by norm kernel
            const int col = c * CK + g * 8 + tq * 2;
            *(float2*)(Pb + (size_t)(q0 + r0) * SEQ + col) = make_float2(p0, p1);
            *(float2*)(Pb + (size_t)(q0 + r1) * SEQ + col) = make_float2(p2, p3);

            // C-frag -> A-frag quad transpose (width 4), tf32-rounded
            unsigned u0 = tf32u(p0), u1 = tf32u(p1), u2 = tf32u(p2), u3 = tf32u(p3);
            unsigned afr[4];
            {
                unsigned x0 = __shfl_sync(0xffffffffu, u0, s0, 4);
                unsigned x1 = __shfl_sync(0xffffffffu, u1, s0, 4);
                afr[0] = par ? x1 : x0;
                unsigned y0 = __shfl_sync(0xffffffffu, u0, s0 + 2, 4);
                unsigned y1 = __shfl_sync(0xffffffffu, u1, s0 + 2, 4);
                afr[2] = par ? y1 : y0;
                unsigned x2 = __shfl_sync(0xffffffffu, u2, s0, 4);
                unsigned x3 = __shfl_sync(0xffffffffu, u3, s0, 4);
                afr[1] = par ? x3 : x2;
                unsigned y2 = __shfl_sync(0xffffffffu, u2, s0 + 2, 4);
                unsigned y3 = __shfl_sync(0xffffffffu, u3, s0 + 2, 4);
                afr[3] = par ? y3 : y2;
            }
            const float2* Vr = Vf + (g * 4 + tq) * 68 + tg;
#pragma unroll
            for (int nv = 0; nv < 8; nv++) {
                float2 vb = Vr[nv * 8];
                unsigned b[2] = {__float_as_uint(vb.x), __float_as_uint(vb.y)};
                mma_tf32(acc[nv], afr, b);
            }
        }
        __syncthreads();
    }

    // row sums -> inverses (quad reduce)
    ls0 += __shfl_xor_sync(0xffffffffu, ls0, 1);
    ls0 += __shfl_xor_sync(0xffffffffu, ls0, 2);
    ls1 += __shfl_xor_sync(0xffffffffu, ls1, 1);
    ls1 += __shfl_xor_sync(0xffffffffu, ls1, 2);
    const float inv0 = 1.f / fmaxf(ls0, 1e-37f);
    const float inv1 = 1.f / fmaxf(ls1, 1e-37f);
    if (tq == 0) {
        g_linv[bh * SEQ + q0 + r0] = inv0;
        g_linv[bh * SEQ + q0 + r1] = inv1;
    }

    // epilogue: ctx = acc / l
#pragma unroll
    for (int nv = 0; nv < 8; nv++) {
        const int col = nv * 8 + tq * 2;
        *(float2*)(Cb + (size_t)(q0 + r0) * DH + col) =
            make_float2(acc[nv][0] * inv0, acc[nv][1] * inv0);
        *(float2*)(Cb + (size_t)(q0 + r1) * DH + col) =
            make_float2(acc[nv][2] * inv1, acc[nv][3] * inv1);
    }
}

// streaming normalize: prob[i] *= linv[row(i)]
__global__ void __launch_bounds__(256)
norm_kernel(float4* __restrict__ p4) {
    const size_t n4 = (size_t)32 * SEQ * SEQ / 4;
    size_t i = (size_t)blockIdx.x * blockDim.x + threadIdx.x;
    const size_t step = (size_t)gridDim.x * blockDim.x;
    for (; i < n4; i += step) {
        const float s = g_linv[i >> 9];
        float4 v = p4[i];
        v.x *= s; v.y *= s; v.z *= s; v.w *= s;
        p4[i] = v;
    }
}

extern "C" void kernel_launch(void* const* d_in, const int* in_sizes, int n_in,
                              void* d_out, int out_size) {
    const float* Q = (const float*)d_in[0];
    const float* K = (const float*)d_in[1];
    const float* V = (const float*)d_in[2];
    const void* mask = d_in[3];

    float* ctx = (float*)d_out;                      // [2,16,2048,64]
    float* prob = ctx + (size_t)32 * SEQ * DH;       // [2,16,2048,2048]

    cudaFuncSetAttribute(attn_main, cudaFuncAttributeMaxDynamicSharedMemorySize, SM_TOTAL);
    dim3 grid(SEQ / 128, 32);
    attn_main<<<grid, NTH, SM_TOTAL>>>(Q, K, V, mask, prob, ctx);
    norm_kernel<<<16384, 256>>>((float4*)prob);
}

// round 13
// speedup vs baseline: 1.0550x; 1.0550x over previous
#include <cuda_runtime.h>
#include <cstdint>

#define SEQ 2048
#define DH 64
#define NTH 256
#define CLS2 23.0f           // fixed shift in log2 domain; |s2| <~ 8.5 << 23
#define CK 64
#define NCH (SEQ / CK)
#define QSCALE 0.18033688f   // 0.125 * log2(e)

// smem byte offsets (single pass)
#define OFF_K0 0             // K tile: 64*68*4 = 17408 (slot 18432)
#define OFF_K1 18432
#define OFF_V0 36864         // V tile: 64*72*4 = 18432
#define OFF_V1 55296
#define OFF_MB 73728         // per-warp mask words: 8*34*4 = 1088
#define OFF_INV 74816        // row inverses: 128*4 = 512
#define SM_TOTAL 75328

__device__ __forceinline__ float tf32f(float x) {
    unsigned u; asm("cvt.rna.tf32.f32 %0, %1;" : "=r"(u) : "f"(x));
    return __uint_as_float(u);
}
__device__ __forceinline__ unsigned tf32u(float x) {
    unsigned u; asm("cvt.rna.tf32.f32 %0, %1;" : "=r"(u) : "f"(x));
    return u;
}
__device__ __forceinline__ float ex2(float x) {
    float r; asm("ex2.approx.ftz.f32 %0, %1;" : "=f"(r) : "f"(x));
    return r;
}
__device__ __forceinline__ void mma_tf32(float* c, const unsigned* a, const unsigned* b) {
    asm volatile(
        "mma.sync.aligned.m16n8k8.row.col.f32.tf32.tf32.f32 "
        "{%0,%1,%2,%3}, {%4,%5,%6,%7}, {%8,%9}, {%0,%1,%2,%3};"
        : "+f"(c[0]), "+f"(c[1]), "+f"(c[2]), "+f"(c[3])
        : "r"(a[0]), "r"(a[1]), "r"(a[2]), "r"(a[3]), "r"(b[0]), "r"(b[1]));
}
__device__ __forceinline__ bool mask_is_int32(const unsigned* m) {
    unsigned acc = 0;
#pragma unroll
    for (int i = 0; i < 64; i++) acc |= m[i];
    return acc <= 1u;
}

// gmem [64][64] f32 chunk -> smem tile (rna tf32), row stride strd floats
__device__ __forceinline__ void stage_f32(const float* __restrict__ src, float* __restrict__ dst,
                                          int strd) {
#pragma unroll
    for (int i = 0; i < 4; i++) {
        int u = threadIdx.x + i * NTH;
        int r = u >> 4, s = (u & 15) * 4;
        float4 v = *(const float4*)(src + (size_t)r * DH + s);
        *(float4*)(dst + r * strd + s) =
            make_float4(tf32f(v.x), tf32f(v.y), tf32f(v.z), tf32f(v.w));
    }
}

__global__ void __launch_bounds__(NTH, 2)
attn_main(const float* __restrict__ Q, const float* __restrict__ K,
          const float* __restrict__ V, const void* __restrict__ mraw,
          float* __restrict__ prob, float* __restrict__ ctx) {
    extern __shared__ char smem[];
    const int tid = threadIdx.x, w = tid >> 5, lane = tid & 31;
    const int tg = lane >> 2, tq = lane & 3;
    const int bh = blockIdx.y, q0 = blockIdx.x * 128;

    const float* Qb = Q + (size_t)bh * SEQ * DH;
    const float* Kb = K + (size_t)bh * SEQ * DH;
    const float* Vb = V + (size_t)bh * SEQ * DH;
    float* Pb = prob + (size_t)bh * SEQ * SEQ;
    float* Cb = ctx + (size_t)bh * SEQ * DH;

    const bool m32 = mask_is_int32((const unsigned*)mraw);
    const int r0 = w * 16 + tg, r1 = r0 + 8;

    // ---- prologue: Q -> smem (transient) -> tf32 frags ----
    {
        float* Qs = (float*)smem;
#pragma unroll
        for (int i = 0; i < 8; i++) {
            int u = tid + i * NTH;
            int r = u >> 4, c4 = (u & 15) * 4;
            *(float4*)(Qs + r * 64 + c4) = *(const float4*)(Qb + (size_t)(q0 + r) * DH + c4);
        }
    }
    __syncthreads();
    unsigned aQ[8][4];
    {
        const float* Qs = (const float*)smem;
        const float* q0p = Qs + r0 * 64;
        const float* q1p = Qs + r1 * 64;
#pragma unroll
        for (int ks = 0; ks < 8; ks++) {
            int j = ks * 8 + tq;
            aQ[ks][0] = tf32u(q0p[j] * QSCALE);
            aQ[ks][1] = tf32u(q1p[j] * QSCALE);
            aQ[ks][2] = tf32u(q0p[j + 4] * QSCALE);
            aQ[ks][3] = tf32u(q1p[j + 4] * QSCALE);
        }
    }
    __syncthreads();

    // stage chunk 0
    stage_f32(Kb, (float*)(smem + OFF_K0), 68);
    stage_f32(Vb, (float*)(smem + OFF_V0), 72);
    __syncthreads();

    float acc[8][4];
#pragma unroll
    for (int nv = 0; nv < 8; nv++) {
        acc[nv][0] = 0.f; acc[nv][1] = 0.f; acc[nv][2] = 0.f; acc[nv][3] = 0.f;
    }
    float ls0 = 0.f, ls1 = 0.f;
    const int s0 = tq >> 1, par = tq & 1;
    unsigned* MB = (unsigned*)(smem + OFF_MB) + w * 34;

    for (int c = 0; c < NCH; c++) {
        // inline mask ballots: this warp's 16 rows x 64 cols -> 32 words
        if (m32) {
            const int* Mi = (const int*)mraw + (size_t)bh * SEQ * SEQ;
#pragma unroll 4
            for (int j = 0; j < 16; j++) {
                const int* row = Mi + (size_t)(q0 + w * 16 + j) * SEQ + c * CK;
                unsigned b0 = __ballot_sync(0xffffffffu, row[lane] != 0);
                unsigned b1 = __ballot_sync(0xffffffffu, row[32 + lane] != 0);
                if (lane == 0) { MB[j * 2] = b0; MB[j * 2 + 1] = b1; }
            }
        } else {
            const unsigned char* Mc = (const unsigned char*)mraw + (size_t)bh * SEQ * SEQ;
#pragma unroll 4
            for (int j = 0; j < 16; j++) {
                const unsigned char* row = Mc + (size_t)(q0 + w * 16 + j) * SEQ + c * CK;
                unsigned b0 = __ballot_sync(0xffffffffu, row[lane] != 0);
                unsigned b1 = __ballot_sync(0xffffffffu, row[32 + lane] != 0);
                if (lane == 0) { MB[j * 2] = b0; MB[j * 2 + 1] = b1; }
            }
        }
        __syncwarp();
        const unsigned mA0 = MB[tg * 2],       mA1 = MB[tg * 2 + 1];
        const unsigned mB0 = MB[(tg + 8) * 2], mB1 = MB[(tg + 8) * 2 + 1];

        const float* Kf = (const float*)(smem + ((c & 1) ? OFF_K1 : OFF_K0));
        const float* Vf = (const float*)(smem + ((c & 1) ? OFF_V1 : OFF_V0));

#pragma unroll
        for (int g = 0; g < 8; g++) {
            float c0[4] = {0.f, 0.f, 0.f, 0.f};
            float c1[4] = {0.f, 0.f, 0.f, 0.f};
            const float* Kr = Kf + (g * 8 + tg) * 68;
#pragma unroll
            for (int ks = 0; ks < 8; ks += 2) {
                unsigned b0[2], b1[2];
                b0[0] = __float_as_uint(Kr[ks * 8 + tq]);
                b0[1] = __float_as_uint(Kr[ks * 8 + tq + 4]);
                b1[0] = __float_as_uint(Kr[ks * 8 + 8 + tq]);
                b1[1] = __float_as_uint(Kr[ks * 8 + 8 + tq + 4]);
                mma_tf32(c0, aQ[ks], b0);
                mma_tf32(c1, aQ[ks + 1], b1);
            }
            const unsigned mw0 = (g < 4) ? mA0 : mA1;
            const unsigned mw1 = (g < 4) ? mB0 : mB1;
            const int sh = (g & 3) * 8 + tq * 2;
            float p0 = ((mw0 >> sh) & 1)       ? 0.f : ex2(c0[0] + c1[0] - CLS2);
            float p1 = ((mw0 >> (sh + 1)) & 1) ? 0.f : ex2(c0[1] + c1[1] - CLS2);
            float p2 = ((mw1 >> sh) & 1)       ? 0.f : ex2(c0[2] + c1[2] - CLS2);
            float p3 = ((mw1 >> (sh + 1)) & 1) ? 0.f : ex2(c0[3] + c1[3] - CLS2);
            ls0 += p0 + p1;
            ls1 += p2 + p3;

            // raw (unnormalized) probs -> gmem; normalized below after l is known
            const int col = c * CK + g * 8 + tq * 2;
            *(float2*)(Pb + (size_t)(q0 + r0) * SEQ + col) = make_float2(p0, p1);
            *(float2*)(Pb + (size_t)(q0 + r1) * SEQ + col) = make_float2(p2, p3);

            // C-frag -> A-frag quad transpose (width 4), tf32-rounded
            unsigned u0 = tf32u(p0), u1 = tf32u(p1), u2 = tf32u(p2), u3 = tf32u(p3);
            unsigned afr[4];
            {
                unsigned x0 = __shfl_sync(0xffffffffu, u0, s0, 4);
                unsigned x1 = __shfl_sync(0xffffffffu, u1, s0, 4);
                afr[0] = par ? x1 : x0;
                unsigned y0 = __shfl_sync(0xffffffffu, u0, s0 + 2, 4);
                unsigned y1 = __shfl_sync(0xffffffffu, u1, s0 + 2, 4);
                afr[2] = par ? y1 : y0;
                unsigned x2 = __shfl_sync(0xffffffffu, u2, s0, 4);
                unsigned x3 = __shfl_sync(0xffffffffu, u3, s0, 4);
                afr[1] = par ? x3 : x2;
                unsigned y2 = __shfl_sync(0xffffffffu, u2, s0 + 2, 4);
                unsigned y3 = __shfl_sync(0xffffffffu, u3, s0 + 2, 4);
                afr[3] = par ? y3 : y2;
            }
            const float* Vr = Vf + (g * 8 + tq) * 72;
#pragma unroll
            for (int nv = 0; nv < 8; nv++) {
                unsigned b[2];
                b[0] = __float_as_uint(Vr[nv * 8 + tg]);
                b[1] = __float_as_uint(Vr[4 * 72 + nv * 8 + tg]);
                mma_tf32(acc[nv], afr, b);
            }
        }
        __syncthreads();
        if (c + 1 < NCH) {
            stage_f32(Kb + (size_t)(c + 1) * CK * DH,
                      (float*)(smem + ((c & 1) ? OFF_K0 : OFF_K1)), 68);
            stage_f32(Vb + (size_t)(c + 1) * CK * DH,
                      (float*)(smem + ((c & 1) ? OFF_V0 : OFF_V1)), 72);
        }
        __syncthreads();
    }

    // row sums -> inverses (quad reduce over tq lanes)
    ls0 += __shfl_xor_sync(0xffffffffu, ls0, 1);
    ls0 += __shfl_xor_sync(0xffffffffu, ls0, 2);
    ls1 += __shfl_xor_sync(0xffffffffu, ls1, 1);
    ls1 += __shfl_xor_sync(0xffffffffu, ls1, 2);
    const float inv0 = 1.f / fmaxf(ls0, 1e-37f);
    const float inv1 = 1.f / fmaxf(ls1, 1e-37f);

    float* sInv = (float*)(smem + OFF_INV);
    if (tq == 0) { sInv[r0] = inv0; sInv[r1] = inv1; }

    // epilogue: ctx = acc / l
#pragma unroll
    for (int nv = 0; nv < 8; nv++) {
        const int col = nv * 8 + tq * 2;
        *(float2*)(Cb + (size_t)(q0 + r0) * DH + col) =
            make_float2(acc[nv][0] * inv0, acc[nv][1] * inv0);
        *(float2*)(Cb + (size_t)(q0 + r1) * DH + col) =
            make_float2(acc[nv][2] * inv1, acc[nv][3] * inv1);
    }
    __syncthreads();

    // ---- fused normalization of this block's own prob span (1 MB, in place) ----
    // span: rows [q0, q0+128) of head bh = contiguous 128*SEQ floats at Pb + q0*SEQ
    {
        float4* p4 = (float4*)(Pb + (size_t)q0 * SEQ);
        // 128 rows * 512 float4/row = 65536 float4; 256 float4 per thread
#pragma unroll 4
        for (int i = tid; i < 128 * (SEQ / 4); i += NTH) {
            const float s = sInv[i >> 9];
            float4 v = p4[i];
            v.x *= s; v.y *= s; v.z *= s; v.w *= s;
            p4[i] = v;
        }
    }
}

extern "C" void kernel_launch(void* const* d_in, const int* in_sizes, int n_in,
                              void* d_out, int out_size) {
    const float* Q = (const float*)d_in[0];
    const float* K = (const float*)d_in[1];
    const float* V = (const float*)d_in[2];
    const void* mask = d_in[3];

    float* ctx = (float*)d_out;                      // [2,16,2048,64]
    float* prob = ctx + (size_t)32 * SEQ * DH;       // [2,16,2048,2048]

    cudaFuncSetAttribute(attn_main, cudaFuncAttributeMaxDynamicSharedMemorySize, SM_TOTAL);
    dim3 grid(SEQ / 128, 32);
    attn_main<<<grid, NTH, SM_TOTAL>>>(Q, K, V, mask, prob, ctx);
}